// round 11
// baseline (speedup 1.0000x reference)
#include <cuda_runtime.h>

// Inverse 2x2 Haar wavelet reconstruction — round 11 (512-thread-block probe,
// resubmit x2; broker at capacity both prior attempts).
//   ll: (16, 64, 128, 128) f32
//   hf: (16, 192, 128, 128) f32 -> (16, 64, 3, 128, 128) = lh, hl, hh
//   out:(16, 64, 256, 256) f32
//
// History:
//   R3: 256 thr/blk, no hints:  79.71us kernel, DRAM 76.5%, occ 76%
//   R4: 2 tiles/thread (MLP 8): 82.72us, occ 51%  <- disqualified
//   R8 (=R5): 256 thr/blk + .cs hints: 79.65us, DRAM 76.2%  <- neutral vs R3
// Converged at ~76% of HBM spec with exactly-mandatory 512 MiB traffic.
// This probe: identical code, 512-thread blocks (4 CTAs/SM instead of 8) to
// reduce per-CTA L1tex queue burst contention per the B300 spread model.
// Same warps/SM, same regs; only CTA granularity changes.

static constexpr int B  = 16;
static constexpr int C  = 64;
static constexpr int H  = 128;
static constexpr int W  = 128;
static constexpr int W4 = W / 4;                               // 32
static constexpr unsigned PLANE4 = (unsigned)H * W4;           // 4096
static constexpr unsigned TOTAL4 = (unsigned)B * C * H * W4;   // 4,194,304 = 8192*512

static constexpr unsigned BLOCK = 512;

__global__ __launch_bounds__(BLOCK)
void ihaar_kernel(const float4* __restrict__ ll4,
                  const float4* __restrict__ hf4,
                  float4* __restrict__ out4)
{
    // exact grid: 8192 blocks * 512 threads == TOTAL4, no bounds check
    unsigned t = blockIdx.x * BLOCK + threadIdx.x;

    unsigned w4 = t & (W4 - 1);            // [0,32)
    unsigned r  = t >> 5;                  // bc*H + h
    unsigned h  = r & (H - 1);
    unsigned bc = r >> 7;                  // b*C + c, [0,1024)

    // ll is bc-major: t IS the ll float4 index.
    // hf plane (3*bc + s): offset = t + 2*bc*PLANE4 (+ s*PLANE4)
    unsigned hf_off = t + 2u * bc * PLANE4;

    // front-batched streaming loads: MLP = 4 per thread
    float4 vll = __ldcs(&ll4[t]);
    float4 vlh = __ldcs(&hf4[hf_off]);
    float4 vhl = __ldcs(&hf4[hf_off + PLANE4]);
    float4 vhh = __ldcs(&hf4[hf_off + 2u * PLANE4]);

    // butterfly, 8 adds/lane via shared subexpressions:
    //   p = ll - lh, q = ll + lh, u = hh - hl, v = hh + hl
    //   a = p + u, b = p - u, c = q - v, d = q + v
    float p0 = vll.x - vlh.x, q0 = vll.x + vlh.x;
    float u0 = vhh.x - vhl.x, v0 = vhh.x + vhl.x;
    float p1 = vll.y - vlh.y, q1 = vll.y + vlh.y;
    float u1 = vhh.y - vhl.y, v1 = vhh.y + vhl.y;
    float p2 = vll.z - vlh.z, q2 = vll.z + vlh.z;
    float u2 = vhh.z - vhl.z, v2 = vhh.z + vhl.z;
    float p3 = vll.w - vlh.w, q3 = vll.w + vlh.w;
    float u3 = vhh.w - vhl.w, v3 = vhh.w + vhl.w;

    // output (B, C, 256, 256): rows 2h, 2h+1; cols start at 8*w4.
    // out row = 64 float4 units.
    unsigned orow0 = (bc * (2u * H) + 2u * h) * 64u + 2u * w4;
    unsigned orow1 = orow0 + 64u;

    __stcs(&out4[orow0],     make_float4(p0 + u0, p0 - u0, p1 + u1, p1 - u1));  // a0 b0 a1 b1
    __stcs(&out4[orow0 + 1], make_float4(p2 + u2, p2 - u2, p3 + u3, p3 - u3));  // a2 b2 a3 b3
    __stcs(&out4[orow1],     make_float4(q0 - v0, q0 + v0, q1 - v1, q1 + v1));  // c0 d0 c1 d1
    __stcs(&out4[orow1 + 1], make_float4(q2 - v2, q2 + v2, q3 - v3, q3 + v3));  // c2 d2 c3 d3
}

extern "C" void kernel_launch(void* const* d_in, const int* in_sizes, int n_in,
                              void* d_out, int out_size)
{
    const float4* ll = (const float4*)d_in[0];
    const float4* hf = (const float4*)d_in[1];
    float4* out = (float4*)d_out;

    ihaar_kernel<<<TOTAL4 / BLOCK, BLOCK>>>(ll, hf, out);
}

// round 12
// speedup vs baseline: 1.0019x; 1.0019x over previous
#include <cuda_runtime.h>

// Inverse 2x2 Haar wavelet reconstruction — FINAL (revert to R8, the best
// measured configuration).
//   ll: (16, 64, 128, 128) f32
//   hf: (16, 192, 128, 128) f32 -> (16, 64, 3, 128, 128) = lh, hl, hh
//   out:(16, 64, 256, 256) f32
//
// Adjudicated experiments:
//   R3:  256 thr/blk, 1 tile/thread:     79.71us, DRAM 76.5%, occ 76%
//   R4:  2 tiles/thread (per-thread MLP=8): 82.72us, occ 51%  <- regress
//   R8:  R3 + .cs streaming hints:       79.65us, DRAM 76.2%  <- BEST
//   R11: 512 thr/blk:                    81.82us, occ 72%     <- regress
// Traffic == mandatory 512 MiB; ~6.05 TB/s = 76% of HBM spec is the practical
// turnaround ceiling for this 4-read/1-write streaming mix. Converged.

static constexpr int B  = 16;
static constexpr int C  = 64;
static constexpr int H  = 128;
static constexpr int W  = 128;
static constexpr int W4 = W / 4;                               // 32
static constexpr unsigned PLANE4 = (unsigned)H * W4;           // 4096
static constexpr unsigned TOTAL4 = (unsigned)B * C * H * W4;   // 4,194,304 = 16384*256

__global__ __launch_bounds__(256)
void ihaar_kernel(const float4* __restrict__ ll4,
                  const float4* __restrict__ hf4,
                  float4* __restrict__ out4)
{
    // exact grid: 16384 blocks * 256 threads == TOTAL4, no bounds check
    unsigned t = blockIdx.x * 256u + threadIdx.x;

    unsigned w4 = t & (W4 - 1);            // [0,32)
    unsigned r  = t >> 5;                  // bc*H + h
    unsigned h  = r & (H - 1);
    unsigned bc = r >> 7;                  // b*C + c, [0,1024)

    // ll is bc-major: t IS the ll float4 index.
    // hf plane (3*bc + s): offset = t + 2*bc*PLANE4 (+ s*PLANE4)
    unsigned hf_off = t + 2u * bc * PLANE4;

    // front-batched streaming loads: MLP = 4 per thread, ~76% occupancy
    float4 vll = __ldcs(&ll4[t]);
    float4 vlh = __ldcs(&hf4[hf_off]);
    float4 vhl = __ldcs(&hf4[hf_off + PLANE4]);
    float4 vhh = __ldcs(&hf4[hf_off + 2u * PLANE4]);

    // butterfly, 8 adds/lane via shared subexpressions:
    //   p = ll - lh, q = ll + lh, u = hh - hl, v = hh + hl
    //   a = p + u, b = p - u, c = q - v, d = q + v
    float p0 = vll.x - vlh.x, q0 = vll.x + vlh.x;
    float u0 = vhh.x - vhl.x, v0 = vhh.x + vhl.x;
    float p1 = vll.y - vlh.y, q1 = vll.y + vlh.y;
    float u1 = vhh.y - vhl.y, v1 = vhh.y + vhl.y;
    float p2 = vll.z - vlh.z, q2 = vll.z + vlh.z;
    float u2 = vhh.z - vhl.z, v2 = vhh.z + vhl.z;
    float p3 = vll.w - vlh.w, q3 = vll.w + vlh.w;
    float u3 = vhh.w - vhl.w, v3 = vhh.w + vhl.w;

    // output (B, C, 256, 256): rows 2h, 2h+1; cols start at 8*w4.
    // out row = 64 float4 units.
    unsigned orow0 = (bc * (2u * H) + 2u * h) * 64u + 2u * w4;
    unsigned orow1 = orow0 + 64u;

    __stcs(&out4[orow0],     make_float4(p0 + u0, p0 - u0, p1 + u1, p1 - u1));  // a0 b0 a1 b1
    __stcs(&out4[orow0 + 1], make_float4(p2 + u2, p2 - u2, p3 + u3, p3 - u3));  // a2 b2 a3 b3
    __stcs(&out4[orow1],     make_float4(q0 - v0, q0 + v0, q1 - v1, q1 + v1));  // c0 d0 c1 d1
    __stcs(&out4[orow1 + 1], make_float4(q2 - v2, q2 + v2, q3 - v3, q3 + v3));  // c2 d2 c3 d3
}

extern "C" void kernel_launch(void* const* d_in, const int* in_sizes, int n_in,
                              void* d_out, int out_size)
{
    const float4* ll = (const float4*)d_in[0];
    const float4* hf = (const float4*)d_in[1];
    float4* out = (float4*)d_out;

    ihaar_kernel<<<TOTAL4 / 256u, 256>>>(ll, hf, out);
}